// round 11
// baseline (speedup 1.0000x reference)
#include <cuda_runtime.h>
#include <cstdint>

// PixelShuffle (depth-to-space, R=2, feature-major grouping)
// in : [B=8, X=256, Y=256, C=256] fp32,  C = F*4, c = f*4 + i*2 + j
// out: [B=8, 2X=512, 2Y=512, F=64] fp32
// out[b, 2x+i, 2y+j, f] = in[b, x, y, 4f + 2i + j]
//
// Each thread handles 4 consecutive features (f0 = 4*fg) of a PAIR of
// y-adjacent pixels (y0 = 2*yp, y1 = 2*yp+1):
//   - 8 float4 loads, front-batched (MLP_p1 = 8)
//   - register transpose (compile-time component selection, free)
//   - 8 float4 stores: per output row, the 4 stores land at consecutive
//     column offsets -> one 256 B contiguous run per thread per row.
//
// (Third submission attempt — rounds 8 and 10 both died to GB300 container
//  infra before running. Kernel source identical; preserves A/B vs R7.)

static constexpr int B = 8;
static constexpr int X = 256;
static constexpr int Y = 256;
static constexpr int F = 64;

__global__ __launch_bounds__(256, 8)
void pixel_shuffle_kernel(const float4* __restrict__ in, float4* __restrict__ out) {
    // tid layout: fg (4 bits), yp (7 bits: y-pair), x (8 bits), b (3 bits)
    const uint32_t tid = blockIdx.x * 256u + threadIdx.x;   // < 8*256*128*16 = 4,194,304

    const uint32_t fg  = tid & 15u;             // f0 = 4*fg
    const uint32_t rest = tid >> 4;
    const uint32_t yp  = rest & 127u;           // y0 = 2*yp, y1 = 2*yp+1
    const uint32_t x   = (rest >> 7) & 255u;
    const uint32_t b   = rest >> 15;

    // Input base (float4 units): pixel (b,x,2*yp) starts at pixBase*64.
    const uint32_t pixBase = (((b << 8) | x) << 8) | (yp << 1);
    const float4* src = in + (pixBase << 6) + (fg << 2);

    // Pixel 0 (y = 2*yp): features f0..f0+3
    const float4 a0 = __ldcs(src + 0);
    const float4 a1 = __ldcs(src + 1);
    const float4 a2 = __ldcs(src + 2);
    const float4 a3 = __ldcs(src + 3);
    // Pixel 1 (y = 2*yp+1): +64 float4 (one pixel = 256 floats)
    const float4 b0 = __ldcs(src + 64);
    const float4 b1 = __ldcs(src + 65);
    const float4 b2 = __ldcs(src + 66);
    const float4 b3 = __ldcs(src + 67);

    // Output base (float4 units): row xr=2x, col yc=4*yp, feature 4*fg.
    //   ((b*512 + 2x)*512 + 4*yp)*16 + fg
    const uint32_t base = (((((b << 9) + (x << 1)) << 9) + (yp << 2)) << 4) + fg;
    const uint32_t rowStride = 512u * 16u;      // one output row in float4 units

    // Row xr = 2x (i=0): columns 4yp+0 (p0,j0), 4yp+1 (p0,j1), 4yp+2 (p1,j0), 4yp+3 (p1,j1)
    __stcs(out + base,                       make_float4(a0.x, a1.x, a2.x, a3.x));
    __stcs(out + base + 16u,                 make_float4(a0.y, a1.y, a2.y, a3.y));
    __stcs(out + base + 32u,                 make_float4(b0.x, b1.x, b2.x, b3.x));
    __stcs(out + base + 48u,                 make_float4(b0.y, b1.y, b2.y, b3.y));
    // Row xr = 2x+1 (i=1): same columns, .z/.w components
    __stcs(out + base + rowStride,           make_float4(a0.z, a1.z, a2.z, a3.z));
    __stcs(out + base + rowStride + 16u,     make_float4(a0.w, a1.w, a2.w, a3.w));
    __stcs(out + base + rowStride + 32u,     make_float4(b0.z, b1.z, b2.z, b3.z));
    __stcs(out + base + rowStride + 48u,     make_float4(b0.w, b1.w, b2.w, b3.w));
}

extern "C" void kernel_launch(void* const* d_in, const int* in_sizes, int n_in,
                              void* d_out, int out_size) {
    const float4* in  = (const float4*)d_in[0];
    float4*       out = (float4*)d_out;

    const uint32_t total  = (uint32_t)B * X * (Y / 2) * (F / 4);  // 4,194,304 threads
    const uint32_t blocks = total / 256u;                         // 16,384
    pixel_shuffle_kernel<<<blocks, 256>>>(in, out);
}

// round 13
// speedup vs baseline: 1.1023x; 1.1023x over previous
#include <cuda_runtime.h>
#include <cstdint>

// PixelShuffle (depth-to-space, R=2, feature-major grouping)
// in : [B=8, X=256, Y=256, C=256] fp32,  C = F*4, c = f*4 + i*2 + j
// out: [B=8, 2X=512, 2Y=512, F=64] fp32
// out[b, 2x+i, 2y+j, f] = in[b, x, y, 4f + 2i + j]
//
// Each thread handles 4 consecutive features (f0 = 4*fg) of one pixel:
//   - 4 consecutive float4 loads (64 B contiguous per thread, MLP=4)
//   - register 4x4 transpose (free: compile-time component selection)
//   - 4 float4 stores, one per output quadrant, 16 B aligned & coalesced
//
// REVERT to R7 configuration: R11's y-pair variant (8 loads/thread, half the
// threads) regressed 158.5 -> 174.4 us (DRAM 86.2% -> 81.6%). At the HBM wall,
// chip-wide warp concurrency with MLP_p1=4 beats deeper per-thread ILP.

static constexpr int B = 8;
static constexpr int X = 256;
static constexpr int Y = 256;
static constexpr int F = 64;

__global__ __launch_bounds__(256, 8)
void pixel_shuffle_kernel(const float4* __restrict__ in, float4* __restrict__ out) {
    // tid layout: fg fastest (4 bits: f-group of 4 features), then y (8), x (8), b (3)
    const uint32_t tid = blockIdx.x * 256u + threadIdx.x;   // < B*X*Y*(F/4) = 8,388,608

    const uint32_t fg  = tid & 15u;           // f0 = 4*fg
    const uint32_t pix = tid >> 4;            // (b*X + x)*Y + y
    const uint32_t y   = pix & 255u;
    const uint32_t x   = (pix >> 8) & 255u;
    const uint32_t b   = pix >> 16;

    // Input (float4 units): pix*64 + 4*fg + k, k = 0..3. 64 B contiguous per thread.
    const float4* src = in + (pix << 6) + (fg << 2);
    const float4 v0 = __ldcs(src + 0);   // feature f0+0: (q00, q01, q10, q11)
    const float4 v1 = __ldcs(src + 1);   // feature f0+1
    const float4 v2 = __ldcs(src + 2);   // feature f0+2
    const float4 v3 = __ldcs(src + 3);   // feature f0+3

    // Output base (float4 units): ((b*512 + 2x)*512 + 2y)*16 + fg.
    const uint32_t base00_f4 = (((((b << 9) + (x << 1)) << 9) | (y << 1)) << 4) + fg;
    const uint32_t rowStride_f4 = 512u * 16u;   // 512*64 floats / 4

    // Quadrant (i=0,j=0): component .x of each feature
    __stcs(out + base00_f4,                        make_float4(v0.x, v1.x, v2.x, v3.x));
    // Quadrant (i=0,j=1): +64 floats = +16 float4
    __stcs(out + base00_f4 + 16u,                  make_float4(v0.y, v1.y, v2.y, v3.y));
    // Quadrant (i=1,j=0): +1 output row
    __stcs(out + base00_f4 + rowStride_f4,         make_float4(v0.z, v1.z, v2.z, v3.z));
    // Quadrant (i=1,j=1)
    __stcs(out + base00_f4 + rowStride_f4 + 16u,   make_float4(v0.w, v1.w, v2.w, v3.w));
}

extern "C" void kernel_launch(void* const* d_in, const int* in_sizes, int n_in,
                              void* d_out, int out_size) {
    const float4* in  = (const float4*)d_in[0];
    float4*       out = (float4*)d_out;

    const uint32_t total  = (uint32_t)B * X * Y * (F / 4);   // 8,388,608 threads
    const uint32_t blocks = total / 256u;                    // 32,768
    pixel_shuffle_kernel<<<blocks, 256>>>(in, out);
}